// round 13
// baseline (speedup 1.0000x reference)
#include <cuda_runtime.h>
#include <math.h>

#define BATCH 8192

// sp layout constants (bank-conflict-free padded layout)
#define RS 20            // row stride in floats
#define PS 324           // plane (channel) stride
#define SS (8 * PS)      // sample stride: 2592 floats

// ---------------------------------------------------------------------------
// Scratch
// ---------------------------------------------------------------------------
__device__ __align__(16) float g_flat[BATCH * 784]; // conv2 output [B,784]
__device__ __align__(16) float g_feat[BATCH * 4];   // fc2 output   [B,4]
__device__ float g_scsh[8];                         // [scale, shift]

__global__ void k_nop() {}

// ---------------------------------------------------------------------------
// tf32 helpers + MMA
// ---------------------------------------------------------------------------
__device__ __forceinline__ unsigned f2tf32(float f) {
    unsigned r; asm("cvt.rna.tf32.f32 %0, %1;" : "=r"(r) : "f"(f)); return r;
}

#define MMA_TF32(d0, d1, d2, d3, a0, a1, a2, a3, b0, b1)                    \
    asm("mma.sync.aligned.m16n8k8.row.col.f32.tf32.tf32.f32 "               \
        "{%0,%1,%2,%3}, {%4,%5,%6,%7}, {%8,%9}, {%0,%1,%2,%3};"             \
        : "+f"(d0), "+f"(d1), "+f"(d2), "+f"(d3)                            \
        : "r"(a0), "r"(a1), "r"(a2), "r"(a3), "r"(b0), "r"(b1))

// ---------------------------------------------------------------------------
// K1: fused conv1(direct)+pool, conv2(tensor-core implicit GEMM, 3xTF32)+pool.
// 2 samples/block, 224 threads = 7 warps; 49 MMA n-tiles = 7 per warp.
// ---------------------------------------------------------------------------
__global__ __launch_bounds__(224, 2)
void k_conv(const float* __restrict__ x,
            const float* __restrict__ w1, const float* __restrict__ b1,
            const float* __restrict__ w2, const float* __restrict__ b2) {
    __shared__ __align__(16) float sx[2][30][32];   // padded input (1920 f)
    __shared__ __align__(16) float sp[2 * SS];      // conv1 pooled out (5184 f)
    __shared__ __align__(16) float sw1p[96];        // conv1 w, [oc][12]
    __shared__ __align__(16) float sw2r[1152];      // conv2 w raw [oc][72]
    __shared__ __align__(16) float sflat[2 * 784];  // output staging
    __shared__ int ipos[392];                       // n -> s*SS + y*RS + x
    __shared__ float sb1[8], sb2[16];

    const int tid = threadIdx.x;
    const int b0 = blockIdx.x * 2;

    for (int i = tid; i < 1920; i += 224) ((float*)sx)[i] = 0.0f;
    for (int i = tid; i < 2 * SS; i += 224) sp[i] = 0.0f;
    for (int i = tid; i < 1152; i += 224) sw2r[i] = w2[i];
    if (tid < 72) sw1p[(tid / 9) * 12 + (tid % 9)] = w1[tid];
    if (tid < 8)  sb1[tid] = b1[tid];
    if (tid < 16) sb2[tid] = b2[tid];
    // n ordering: n = P*4 + q ; P = pooled pos (2 samples x 49), q = quad pos
    for (int i = tid; i < 392; i += 224) {
        int P = i >> 2, q = i & 3;
        int s = P / 49, pl = P % 49;
        int py = pl / 7, px = pl % 7;
        ipos[i] = s * SS + (2 * py + (q >> 1)) * RS + 2 * px + (q & 1);
    }
    __syncthreads();

    for (int i = tid; i < 2 * 784; i += 224) {
        int s = i / 784, r = i % 784;
        sx[s][r / 28 + 1][r % 28 + 1] = x[(b0 + s) * 784 + r];
    }
    __syncthreads();

    // -------- conv1 (1->8) + relu + pool -> sp (direct, proven) --------
    {
        const int oc = tid & 7;
        const int rest = tid >> 3;      // 0..27
        const int y2 = rest % 14;
        const int s = rest / 14;
        float4 wa = *(const float4*)&sw1p[oc * 12];
        float4 wb = *(const float4*)&sw1p[oc * 12 + 4];
        float4 wc = *(const float4*)&sw1p[oc * 12 + 8];
        const float w[9] = {wa.x, wa.y, wa.z, wa.w, wb.x, wb.y, wb.z, wb.w, wc.x};
        const float bias = sb1[oc];
        float* spb = &sp[s * SS + oc * PS + (y2 + 1) * RS];

        #pragma unroll
        for (int xh = 0; xh < 2; xh++) {
            const int SH = xh * 2;
            float a0[14], a1[14];
            #pragma unroll
            for (int i2 = 0; i2 < 14; i2++) { a0[i2] = bias; a1[i2] = bias; }

            #pragma unroll
            for (int r = 0; r < 4; r++) {
                float e[20];
                const float* rp = &sx[s][2 * y2 + r][xh * 12];
                #pragma unroll
                for (int q = 0; q < 5; q++) ((float4*)e)[q] = ((const float4*)rp)[q];
                if (r < 3) {
                    #pragma unroll
                    for (int xx = 0; xx < 14; xx++) {
                        float a = a0[xx];
                        a = fmaf(e[xx + SH],     w[3 * r],     a);
                        a = fmaf(e[xx + SH + 1], w[3 * r + 1], a);
                        a = fmaf(e[xx + SH + 2], w[3 * r + 2], a);
                        a0[xx] = a;
                    }
                }
                if (r >= 1) {
                    #pragma unroll
                    for (int xx = 0; xx < 14; xx++) {
                        float a = a1[xx];
                        a = fmaf(e[xx + SH],     w[3 * (r - 1)],     a);
                        a = fmaf(e[xx + SH + 1], w[3 * (r - 1) + 1], a);
                        a = fmaf(e[xx + SH + 2], w[3 * (r - 1) + 2], a);
                        a1[xx] = a;
                    }
                }
            }
            #pragma unroll
            for (int p = 0; p < 7; p++) {
                float a = fmaxf(a0[2 * p], 0.0f);
                a = fmaxf(a, fmaxf(a0[2 * p + 1], 0.0f));
                a = fmaxf(a, fmaxf(a1[2 * p], 0.0f));
                a = fmaxf(a, fmaxf(a1[2 * p + 1], 0.0f));
                spb[xh * 7 + p + 1] = a;
            }
        }
    }
    __syncthreads();

    // -------- conv2 via m16n8k8 tf32 MMA (3xTF32 split) --------
    {
        const int lane = tid & 31, warp = tid >> 5;
        const int g = lane >> 2;     // groupID: oc rows (g, g+8); B col (n)
        const int t = lane & 3;      // threadID_in_group: k rows (t, t+4)

        unsigned ahi[36], alo[36];
        int koff0[9], koff1[9];
        #pragma unroll
        for (int kt = 0; kt < 9; kt++) {
            int k0 = kt * 8 + t, k1 = k0 + 4;
            float f0 = sw2r[g * 72 + k0];
            float f1 = sw2r[(g + 8) * 72 + k0];
            float f2 = sw2r[g * 72 + k1];
            float f3 = sw2r[(g + 8) * 72 + k1];
            unsigned h0 = f2tf32(f0), h1 = f2tf32(f1), h2 = f2tf32(f2), h3 = f2tf32(f3);
            ahi[kt * 4 + 0] = h0; ahi[kt * 4 + 1] = h1;
            ahi[kt * 4 + 2] = h2; ahi[kt * 4 + 3] = h3;
            alo[kt * 4 + 0] = f2tf32(f0 - __uint_as_float(h0));
            alo[kt * 4 + 1] = f2tf32(f1 - __uint_as_float(h1));
            alo[kt * 4 + 2] = f2tf32(f2 - __uint_as_float(h2));
            alo[kt * 4 + 3] = f2tf32(f3 - __uint_as_float(h3));
            int ic0 = k0 / 9, r0 = k0 % 9;
            koff0[kt] = ic0 * PS + (r0 / 3) * RS + (r0 % 3);
            int ic1 = k1 / 9, r1 = k1 % 9;
            koff1[kt] = ic1 * PS + (r1 / 3) * RS + (r1 % 3);
        }
        const float bias0 = sb2[g], bias1 = sb2[g + 8];

        for (int tile = warp * 7; tile < warp * 7 + 7; tile++) {
            const int po = ipos[tile * 8 + g];
            float d0 = 0.0f, d1 = 0.0f, d2 = 0.0f, d3 = 0.0f;
            #pragma unroll
            for (int kt = 0; kt < 9; kt++) {
                float b0f = sp[po + koff0[kt]];
                float b1f = sp[po + koff1[kt]];
                unsigned b0h = f2tf32(b0f);
                unsigned b1h = f2tf32(b1f);
                unsigned b0l = f2tf32(b0f - __uint_as_float(b0h));
                unsigned b1l = f2tf32(b1f - __uint_as_float(b1h));
                MMA_TF32(d0, d1, d2, d3,
                         ahi[kt*4+0], ahi[kt*4+1], ahi[kt*4+2], ahi[kt*4+3],
                         b0h, b1h);
                MMA_TF32(d0, d1, d2, d3,
                         ahi[kt*4+0], ahi[kt*4+1], ahi[kt*4+2], ahi[kt*4+3],
                         b0l, b1l);
                MMA_TF32(d0, d1, d2, d3,
                         alo[kt*4+0], alo[kt*4+1], alo[kt*4+2], alo[kt*4+3],
                         b0h, b1h);
            }
            // bias + relu + pool: cols (2t, 2t+1) are a q-pair; shfl_xor(1)
            // merges the other q-pair of the same pooled output P.
            float v0 = fmaxf(fmaxf(d0 + bias0, 0.0f), fmaxf(d1 + bias0, 0.0f));
            float v1 = fmaxf(fmaxf(d2 + bias1, 0.0f), fmaxf(d3 + bias1, 0.0f));
            float o0 = fmaxf(v0, __shfl_xor_sync(0xffffffff, v0, 1));
            float o1 = fmaxf(v1, __shfl_xor_sync(0xffffffff, v1, 1));
            if ((t & 1) == 0) {
                int P = tile * 2 + (t >> 1);
                int s = (P >= 49) ? 1 : 0;
                int pl = P - 49 * s;
                sflat[s * 784 + g * 49 + pl] = o0;
                sflat[s * 784 + (g + 8) * 49 + pl] = o1;
            }
        }
    }
    __syncthreads();

    {
        float4* dst = (float4*)&g_flat[b0 * 784];
        const float4* src = (const float4*)sflat;
        for (int i = tid; i < 392; i += 224) dst[i] = src[i];
    }
}

// ---------------------------------------------------------------------------
// K2: FC1(784->64)+relu + FC2(64->4), tiled GEMM + register prefetch (R12).
// ---------------------------------------------------------------------------
#define FCS 60
__global__ __launch_bounds__(256)
void k_fc(const float* __restrict__ fc1_w, const float* __restrict__ fc1_b,
          const float* __restrict__ fc2_w, const float* __restrict__ fc2_b) {
    __shared__ __align__(16) float sAW[2 * 64 * FCS];
    __shared__ float sw2[256];

    const int tid = threadIdx.x;
    const int s0 = blockIdx.x * 64;
    const int jj = tid & 31;
    const int ss = tid >> 5;
    const float* sW = sAW + 64 * FCS;

    sw2[tid] = fc2_w[tid];

    const float* src[7];
    int dst[7];
    #pragma unroll
    for (int j = 0; j < 7; j++) {
        int i = tid + 256 * j;
        if (i < 896) {
            int r = i / 14, q = i % 14;
            src[j] = &g_flat[(s0 + r) * 784 + q * 4];
            dst[j] = r * FCS + q * 4;
        } else {
            int i2 = i - 896;
            int r = i2 / 14, q = i2 % 14;
            src[j] = &fc1_w[r * 784 + q * 4];
            dst[j] = 64 * FCS + r * FCS + q * 4;
        }
    }

    float4 pf[7];
    #pragma unroll
    for (int j = 0; j < 7; j++) { pf[j] = *(const float4*)src[j]; src[j] += 56; }

    float acc[2][8];
    #pragma unroll
    for (int u = 0; u < 8; u++) { acc[0][u] = 0.0f; acc[1][u] = 0.0f; }

    for (int t = 0; t < 14; t++) {
        __syncthreads();
        #pragma unroll
        for (int j = 0; j < 7; j++) *(float4*)&sAW[dst[j]] = pf[j];
        __syncthreads();
        if (t < 13) {
            #pragma unroll
            for (int j = 0; j < 7; j++) { pf[j] = *(const float4*)src[j]; src[j] += 56; }
        }
        #pragma unroll
        for (int k4 = 0; k4 < 14; k4++) {
            float4 w0 = *(const float4*)&sW[jj * FCS + k4 * 4];
            float4 w1 = *(const float4*)&sW[(jj + 32) * FCS + k4 * 4];
            #pragma unroll
            for (int u = 0; u < 8; u++) {
                float4 a = *(const float4*)&sAW[(ss * 8 + u) * FCS + k4 * 4];
                float t0 = acc[0][u], t1 = acc[1][u];
                t0 = fmaf(a.x, w0.x, t0); t1 = fmaf(a.x, w1.x, t1);
                t0 = fmaf(a.y, w0.y, t0); t1 = fmaf(a.y, w1.y, t1);
                t0 = fmaf(a.z, w0.z, t0); t1 = fmaf(a.z, w1.z, t1);
                t0 = fmaf(a.w, w0.w, t0); t1 = fmaf(a.w, w1.w, t1);
                acc[0][u] = t0; acc[1][u] = t1;
            }
        }
    }

    __syncthreads();
    float* sh = sAW;
    const float bj0 = fc1_b[jj], bj1 = fc1_b[jj + 32];
    #pragma unroll
    for (int u = 0; u < 8; u++) {
        sh[(ss * 8 + u) * 65 + jj]      = fmaxf(acc[0][u] + bj0, 0.0f);
        sh[(ss * 8 + u) * 65 + jj + 32] = fmaxf(acc[1][u] + bj1, 0.0f);
    }
    __syncthreads();

    {
        const int s = tid >> 2, c = tid & 3;
        float a = fc2_b[c];
        const float* hp = &sh[s * 65];
        const float* wc = &sw2[c * 64];
        #pragma unroll
        for (int j = 0; j < 64; j++) a = fmaf(hp[j], wc[j], a);
        g_feat[(s0 + s) * 4 + c] = a;
    }
}

// ---------------------------------------------------------------------------
// K3: batch mean/var -> scale/shift
// ---------------------------------------------------------------------------
__global__ void k_stats(const float* __restrict__ bn_g,
                        const float* __restrict__ bn_b) {
    __shared__ double ss[256][8];
    const int tid = threadIdx.x;
    double sum[4] = {0, 0, 0, 0}, sq[4] = {0, 0, 0, 0};
    for (int s = tid; s < BATCH; s += 256) {
        float4 f = ((const float4*)g_feat)[s];
        double v;
        v = (double)f.x; sum[0] += v; sq[0] += v * v;
        v = (double)f.y; sum[1] += v; sq[1] += v * v;
        v = (double)f.z; sum[2] += v; sq[2] += v * v;
        v = (double)f.w; sum[3] += v; sq[3] += v * v;
    }
    #pragma unroll
    for (int c = 0; c < 4; c++) { ss[tid][c] = sum[c]; ss[tid][4 + c] = sq[c]; }
    __syncthreads();
    for (int off = 128; off >= 1; off >>= 1) {
        if (tid < off) {
            #pragma unroll
            for (int k = 0; k < 8; k++) ss[tid][k] += ss[tid + off][k];
        }
        __syncthreads();
    }
    if (tid < 4) {
        double m = ss[0][tid] / (double)BATCH;
        double var = ss[0][4 + tid] / (double)BATCH - m * m;
        float scale = (float)((double)bn_g[tid] / sqrt(var + 1e-5));
        float shift = bn_b[tid] - (float)m * scale;
        g_scsh[tid] = scale;
        g_scsh[4 + tid] = shift;
    }
}

// ---------------------------------------------------------------------------
// K4: quantum state-vector sim + PauliZ measurement
// ---------------------------------------------------------------------------
template <int STR>
__device__ __forceinline__ void rot_rx(float* sr, float* si, float c, float s) {
    #pragma unroll
    for (int k = 0; k < 16; k++) {
        if (k & STR) continue;
        int k1 = k | STR;
        float ar0 = sr[k], ai0 = si[k], ar1 = sr[k1], ai1 = si[k1];
        sr[k]  = c * ar0 + s * ai1;
        si[k]  = c * ai0 - s * ar1;
        sr[k1] = s * ai0 + c * ar1;
        si[k1] = -s * ar0 + c * ai1;
    }
}

template <int STR>
__device__ __forceinline__ void rot_ry(float* sr, float* si, float c, float s) {
    #pragma unroll
    for (int k = 0; k < 16; k++) {
        if (k & STR) continue;
        int k1 = k | STR;
        float ar0 = sr[k], ai0 = si[k], ar1 = sr[k1], ai1 = si[k1];
        sr[k]  = c * ar0 - s * ar1;
        si[k]  = c * ai0 - s * ai1;
        sr[k1] = s * ar0 + c * ar1;
        si[k1] = s * ai0 + c * ai1;
    }
}

template <int STR>
__device__ __forceinline__ void rot_rz(float* sr, float* si, float c, float s) {
    #pragma unroll
    for (int k = 0; k < 16; k++) {
        float ar = sr[k], ai = si[k];
        if (k & STR) { sr[k] = c * ar - s * ai; si[k] = c * ai + s * ar; }
        else         { sr[k] = c * ar + s * ai; si[k] = c * ai - s * ar; }
    }
}

__device__ __forceinline__ void cnot_c3_t0(float* sr, float* si) {
    #pragma unroll
    for (int k = 1; k < 8; k += 2) {
        int k1 = k | 8;
        float tr = sr[k], ti = si[k];
        sr[k] = sr[k1]; si[k] = si[k1];
        sr[k1] = tr;    si[k1] = ti;
    }
}

__global__ void k_quantum(const float* __restrict__ rl_params,
                          float* __restrict__ out) {
    __shared__ float gc[23], gs[23];
    const int tid = threadIdx.x;
    if (tid < 23) {
        float t = rl_params[tid] * 0.5f;
        gc[tid] = cosf(t);
        gs[tid] = sinf(t);
    }
    __syncthreads();

    const int b = blockIdx.x * blockDim.x + tid;
    if (b >= BATCH) return;

    float sr[16], si[16];
    #pragma unroll
    for (int k = 0; k < 16; k++) { sr[k] = 0.0f; si[k] = 0.0f; }
    sr[0] = 1.0f;

    float4 f4 = ((const float4*)g_feat)[b];
    {
        float f, s, c;
        f = (f4.x * g_scsh[0] + g_scsh[4]) * 0.5f; s = sinf(f); c = cosf(f);
        rot_rx<8>(sr, si, c, s);
        f = (f4.y * g_scsh[1] + g_scsh[5]) * 0.5f; s = sinf(f); c = cosf(f);
        rot_rx<4>(sr, si, c, s);
        f = (f4.z * g_scsh[2] + g_scsh[6]) * 0.5f; s = sinf(f); c = cosf(f);
        rot_rx<2>(sr, si, c, s);
        f = (f4.w * g_scsh[3] + g_scsh[7]) * 0.5f; s = sinf(f); c = cosf(f);
        rot_rx<1>(sr, si, c, s);
    }

    #pragma unroll
    for (int r = 0; r < 7; r++) {
        rot_rx<8>(sr, si, gc[3 * r],     gs[3 * r]);
        rot_ry<4>(sr, si, gc[3 * r + 1], gs[3 * r + 1]);
        rot_rz<2>(sr, si, gc[3 * r + 2], gs[3 * r + 2]);
        cnot_c3_t0(sr, si);
    }
    rot_rx<8>(sr, si, gc[21], gs[21]);
    rot_ry<4>(sr, si, gc[22], gs[22]);

    float p[16];
    #pragma unroll
    for (int k = 0; k < 16; k++) p[k] = sr[k] * sr[k] + si[k] * si[k];
    #pragma unroll
    for (int w = 0; w < 4; w++) {
        int str = 8 >> w;
        float acc = 0.0f;
        #pragma unroll
        for (int k = 0; k < 16; k++) acc += (k & str) ? -p[k] : p[k];
        out[b * 4 + w] = acc;
    }
}

// ---------------------------------------------------------------------------
// Launch (3 dummies so ncu's profiled launch, index 3, is the NEW k_conv)
// ---------------------------------------------------------------------------
extern "C" void kernel_launch(void* const* d_in, const int* in_sizes, int n_in,
                              void* d_out, int out_size) {
    const float* x       = (const float*)d_in[0];
    const float* conv1_w = (const float*)d_in[1];
    const float* conv1_b = (const float*)d_in[2];
    const float* conv2_w = (const float*)d_in[3];
    const float* conv2_b = (const float*)d_in[4];
    const float* fc1_w   = (const float*)d_in[5];
    const float* fc1_b   = (const float*)d_in[6];
    const float* fc2_w   = (const float*)d_in[7];
    const float* fc2_b   = (const float*)d_in[8];
    const float* bn_g    = (const float*)d_in[9];
    const float* bn_b    = (const float*)d_in[10];
    const float* rl      = (const float*)d_in[11];
    float* out = (float*)d_out;

    k_nop<<<1, 32>>>();
    k_nop<<<1, 32>>>();
    k_nop<<<1, 32>>>();
    k_conv<<<BATCH / 2, 224>>>(x, conv1_w, conv1_b, conv2_w, conv2_b);
    k_fc<<<BATCH / 64, 256>>>(fc1_w, fc1_b, fc2_w, fc2_b);
    k_stats<<<1, 256>>>(bn_g, bn_b);
    k_quantum<<<BATCH / 256, 256>>>(rl, out);
}

// round 14
// speedup vs baseline: 1.0272x; 1.0272x over previous
#include <cuda_runtime.h>
#include <math.h>

#define BATCH 8192

// sp layout constants (padded)
#define RS 20            // row stride in "elements"
#define PS 324           // plane (channel) stride
#define SS (8 * PS)      // sample stride: 2592 elements
// sphl holds float2 (tf32hi, tf32lo) per element -> 2*SS float2 = 41.5KB

// ---------------------------------------------------------------------------
// Scratch
// ---------------------------------------------------------------------------
__device__ __align__(16) float g_flat[BATCH * 784]; // conv2 output [B,784]
__device__ __align__(16) float g_feat[BATCH * 4];   // fc2 output   [B,4]
__device__ float g_scsh[8];                         // [scale, shift]

__global__ void k_nop() {}

// ---------------------------------------------------------------------------
// tf32 helpers + MMA
// ---------------------------------------------------------------------------
__device__ __forceinline__ unsigned f2tf32(float f) {
    unsigned r; asm("cvt.rna.tf32.f32 %0, %1;" : "=r"(r) : "f"(f)); return r;
}

#define MMA_TF32(d0, d1, d2, d3, a0, a1, a2, a3, b0, b1)                    \
    asm("mma.sync.aligned.m16n8k8.row.col.f32.tf32.tf32.f32 "               \
        "{%0,%1,%2,%3}, {%4,%5,%6,%7}, {%8,%9}, {%0,%1,%2,%3};"             \
        : "+f"(d0), "+f"(d1), "+f"(d2), "+f"(d3)                            \
        : "r"(a0), "r"(a1), "r"(a2), "r"(a3), "r"(b0), "r"(b1))

// ---------------------------------------------------------------------------
// K1: fused conv1(direct)+pool -> pre-split tf32 hi/lo planes,
//     conv2 = tensor-core implicit GEMM (3xTF32), loop has ZERO conversions.
// 2 samples/block, 224 threads = 7 warps; 49 MMA n-tiles = 7 per warp.
// ---------------------------------------------------------------------------
__global__ __launch_bounds__(224, 2)
void k_conv(const float* __restrict__ x,
            const float* __restrict__ w1, const float* __restrict__ b1,
            const float* __restrict__ w2, const float* __restrict__ b2) {
    __shared__ __align__(16) float sx[2][30][32];    // padded input (1920 f)
    __shared__ __align__(16) float2 sphl[2 * SS];    // conv1 out, (hi,lo) tf32
    __shared__ __align__(16) float sw1p[96];         // conv1 w, [oc][12]
    __shared__ __align__(16) float sw2r[1152];       // conv2 w raw [oc][72]
    __shared__ __align__(16) float sflat[2 * 784];   // output staging
    __shared__ int ipos[392];                        // n -> s*SS + y*RS + x
    __shared__ float sb1[8], sb2[16];

    const int tid = threadIdx.x;
    const int b0 = blockIdx.x * 2;

    for (int i = tid; i < 1920; i += 224) ((float*)sx)[i] = 0.0f;
    for (int i = tid; i < 2 * SS; i += 224) sphl[i] = make_float2(0.0f, 0.0f);
    for (int i = tid; i < 1152; i += 224) sw2r[i] = w2[i];
    if (tid < 72) sw1p[(tid / 9) * 12 + (tid % 9)] = w1[tid];
    if (tid < 8)  sb1[tid] = b1[tid];
    if (tid < 16) sb2[tid] = b2[tid];
    // n ordering: n = P*4 + q ; P = pooled pos (2 samples x 49), q = quad pos
    for (int i = tid; i < 392; i += 224) {
        int P = i >> 2, q = i & 3;
        int s = P / 49, pl = P % 49;
        int py = pl / 7, px = pl % 7;
        ipos[i] = s * SS + (2 * py + (q >> 1)) * RS + 2 * px + (q & 1);
    }
    __syncthreads();

    for (int i = tid; i < 2 * 784; i += 224) {
        int s = i / 784, r = i % 784;
        sx[s][r / 28 + 1][r % 28 + 1] = x[(b0 + s) * 784 + r];
    }
    __syncthreads();

    // -------- conv1 (1->8) + relu + pool -> sphl (pre-split tf32) --------
    {
        const int oc = tid & 7;
        const int rest = tid >> 3;      // 0..27
        const int y2 = rest % 14;
        const int s = rest / 14;
        float4 wa = *(const float4*)&sw1p[oc * 12];
        float4 wb = *(const float4*)&sw1p[oc * 12 + 4];
        float4 wc = *(const float4*)&sw1p[oc * 12 + 8];
        const float w[9] = {wa.x, wa.y, wa.z, wa.w, wb.x, wb.y, wb.z, wb.w, wc.x};
        const float bias = sb1[oc];
        float2* spb = &sphl[s * SS + oc * PS + (y2 + 1) * RS];

        #pragma unroll
        for (int xh = 0; xh < 2; xh++) {
            const int SH = xh * 2;
            float a0[14], a1[14];
            #pragma unroll
            for (int i2 = 0; i2 < 14; i2++) { a0[i2] = bias; a1[i2] = bias; }

            #pragma unroll
            for (int r = 0; r < 4; r++) {
                float e[20];
                const float* rp = &sx[s][2 * y2 + r][xh * 12];
                #pragma unroll
                for (int q = 0; q < 5; q++) ((float4*)e)[q] = ((const float4*)rp)[q];
                if (r < 3) {
                    #pragma unroll
                    for (int xx = 0; xx < 14; xx++) {
                        float a = a0[xx];
                        a = fmaf(e[xx + SH],     w[3 * r],     a);
                        a = fmaf(e[xx + SH + 1], w[3 * r + 1], a);
                        a = fmaf(e[xx + SH + 2], w[3 * r + 2], a);
                        a0[xx] = a;
                    }
                }
                if (r >= 1) {
                    #pragma unroll
                    for (int xx = 0; xx < 14; xx++) {
                        float a = a1[xx];
                        a = fmaf(e[xx + SH],     w[3 * (r - 1)],     a);
                        a = fmaf(e[xx + SH + 1], w[3 * (r - 1) + 1], a);
                        a = fmaf(e[xx + SH + 2], w[3 * (r - 1) + 2], a);
                        a1[xx] = a;
                    }
                }
            }
            #pragma unroll
            for (int p = 0; p < 7; p++) {
                float a = fmaxf(a0[2 * p], 0.0f);
                a = fmaxf(a, fmaxf(a0[2 * p + 1], 0.0f));
                a = fmaxf(a, fmaxf(a1[2 * p], 0.0f));
                a = fmaxf(a, fmaxf(a1[2 * p + 1], 0.0f));
                unsigned h = f2tf32(a);
                float hf = __uint_as_float(h);
                unsigned l = f2tf32(a - hf);
                spb[xh * 7 + p + 1] = make_float2(hf, __uint_as_float(l));
            }
        }
    }
    __syncthreads();

    // -------- conv2 via m16n8k8 tf32 MMA (3xTF32), zero-cvt inner loop ----
    {
        const int lane = tid & 31, warp = tid >> 5;
        const int g = lane >> 2;     // groupID: oc rows (g, g+8); B col (n)
        const int t = lane & 3;      // threadID_in_group: k rows (t, t+4)

        unsigned ahi[36], alo[36];
        int koff0[9], koff1[9];
        #pragma unroll
        for (int kt = 0; kt < 9; kt++) {
            int k0 = kt * 8 + t, k1 = k0 + 4;
            float f0 = sw2r[g * 72 + k0];
            float f1 = sw2r[(g + 8) * 72 + k0];
            float f2 = sw2r[g * 72 + k1];
            float f3 = sw2r[(g + 8) * 72 + k1];
            unsigned h0 = f2tf32(f0), h1 = f2tf32(f1), h2 = f2tf32(f2), h3 = f2tf32(f3);
            ahi[kt * 4 + 0] = h0; ahi[kt * 4 + 1] = h1;
            ahi[kt * 4 + 2] = h2; ahi[kt * 4 + 3] = h3;
            alo[kt * 4 + 0] = f2tf32(f0 - __uint_as_float(h0));
            alo[kt * 4 + 1] = f2tf32(f1 - __uint_as_float(h1));
            alo[kt * 4 + 2] = f2tf32(f2 - __uint_as_float(h2));
            alo[kt * 4 + 3] = f2tf32(f3 - __uint_as_float(h3));
            int ic0 = k0 / 9, r0 = k0 % 9;
            koff0[kt] = ic0 * PS + (r0 / 3) * RS + (r0 % 3);
            int ic1 = k1 / 9, r1 = k1 % 9;
            koff1[kt] = ic1 * PS + (r1 / 3) * RS + (r1 % 3);
        }
        const float bias0 = sb2[g], bias1 = sb2[g + 8];

        for (int tile = warp * 7; tile < warp * 7 + 7; tile++) {
            const int po = ipos[tile * 8 + g];
            float d0 = 0.0f, d1 = 0.0f, d2 = 0.0f, d3 = 0.0f;
            #pragma unroll
            for (int kt = 0; kt < 9; kt++) {
                float2 v0 = sphl[po + koff0[kt]];
                float2 v1 = sphl[po + koff1[kt]];
                unsigned b0h = __float_as_uint(v0.x);
                unsigned b0l = __float_as_uint(v0.y);
                unsigned b1h = __float_as_uint(v1.x);
                unsigned b1l = __float_as_uint(v1.y);
                MMA_TF32(d0, d1, d2, d3,
                         ahi[kt*4+0], ahi[kt*4+1], ahi[kt*4+2], ahi[kt*4+3],
                         b0h, b1h);
                MMA_TF32(d0, d1, d2, d3,
                         ahi[kt*4+0], ahi[kt*4+1], ahi[kt*4+2], ahi[kt*4+3],
                         b0l, b1l);
                MMA_TF32(d0, d1, d2, d3,
                         alo[kt*4+0], alo[kt*4+1], alo[kt*4+2], alo[kt*4+3],
                         b0h, b1h);
            }
            // bias + relu + pool
            float v0 = fmaxf(fmaxf(d0 + bias0, 0.0f), fmaxf(d1 + bias0, 0.0f));
            float v1 = fmaxf(fmaxf(d2 + bias1, 0.0f), fmaxf(d3 + bias1, 0.0f));
            float o0 = fmaxf(v0, __shfl_xor_sync(0xffffffff, v0, 1));
            float o1 = fmaxf(v1, __shfl_xor_sync(0xffffffff, v1, 1));
            if ((t & 1) == 0) {
                int P = tile * 2 + (t >> 1);
                int s = (P >= 49) ? 1 : 0;
                int pl = P - 49 * s;
                sflat[s * 784 + g * 49 + pl] = o0;
                sflat[s * 784 + (g + 8) * 49 + pl] = o1;
            }
        }
    }
    __syncthreads();

    {
        float4* dst = (float4*)&g_flat[b0 * 784];
        const float4* src = (const float4*)sflat;
        for (int i = tid; i < 392; i += 224) dst[i] = src[i];
    }
}

// ---------------------------------------------------------------------------
// K2: FC1(784->64)+relu + FC2(64->4), tiled GEMM + register prefetch (R12).
// ---------------------------------------------------------------------------
#define FCS 60
__global__ __launch_bounds__(256)
void k_fc(const float* __restrict__ fc1_w, const float* __restrict__ fc1_b,
          const float* __restrict__ fc2_w, const float* __restrict__ fc2_b) {
    __shared__ __align__(16) float sAW[2 * 64 * FCS];
    __shared__ float sw2[256];

    const int tid = threadIdx.x;
    const int s0 = blockIdx.x * 64;
    const int jj = tid & 31;
    const int ss = tid >> 5;
    const float* sW = sAW + 64 * FCS;

    sw2[tid] = fc2_w[tid];

    const float* src[7];
    int dst[7];
    #pragma unroll
    for (int j = 0; j < 7; j++) {
        int i = tid + 256 * j;
        if (i < 896) {
            int r = i / 14, q = i % 14;
            src[j] = &g_flat[(s0 + r) * 784 + q * 4];
            dst[j] = r * FCS + q * 4;
        } else {
            int i2 = i - 896;
            int r = i2 / 14, q = i2 % 14;
            src[j] = &fc1_w[r * 784 + q * 4];
            dst[j] = 64 * FCS + r * FCS + q * 4;
        }
    }

    float4 pf[7];
    #pragma unroll
    for (int j = 0; j < 7; j++) { pf[j] = *(const float4*)src[j]; src[j] += 56; }

    float acc[2][8];
    #pragma unroll
    for (int u = 0; u < 8; u++) { acc[0][u] = 0.0f; acc[1][u] = 0.0f; }

    for (int t = 0; t < 14; t++) {
        __syncthreads();
        #pragma unroll
        for (int j = 0; j < 7; j++) *(float4*)&sAW[dst[j]] = pf[j];
        __syncthreads();
        if (t < 13) {
            #pragma unroll
            for (int j = 0; j < 7; j++) { pf[j] = *(const float4*)src[j]; src[j] += 56; }
        }
        #pragma unroll
        for (int k4 = 0; k4 < 14; k4++) {
            float4 w0 = *(const float4*)&sW[jj * FCS + k4 * 4];
            float4 w1 = *(const float4*)&sW[(jj + 32) * FCS + k4 * 4];
            #pragma unroll
            for (int u = 0; u < 8; u++) {
                float4 a = *(const float4*)&sAW[(ss * 8 + u) * FCS + k4 * 4];
                float t0 = acc[0][u], t1 = acc[1][u];
                t0 = fmaf(a.x, w0.x, t0); t1 = fmaf(a.x, w1.x, t1);
                t0 = fmaf(a.y, w0.y, t0); t1 = fmaf(a.y, w1.y, t1);
                t0 = fmaf(a.z, w0.z, t0); t1 = fmaf(a.z, w1.z, t1);
                t0 = fmaf(a.w, w0.w, t0); t1 = fmaf(a.w, w1.w, t1);
                acc[0][u] = t0; acc[1][u] = t1;
            }
        }
    }

    __syncthreads();
    float* sh = sAW;
    const float bj0 = fc1_b[jj], bj1 = fc1_b[jj + 32];
    #pragma unroll
    for (int u = 0; u < 8; u++) {
        sh[(ss * 8 + u) * 65 + jj]      = fmaxf(acc[0][u] + bj0, 0.0f);
        sh[(ss * 8 + u) * 65 + jj + 32] = fmaxf(acc[1][u] + bj1, 0.0f);
    }
    __syncthreads();

    {
        const int s = tid >> 2, c = tid & 3;
        float a = fc2_b[c];
        const float* hp = &sh[s * 65];
        const float* wc = &sw2[c * 64];
        #pragma unroll
        for (int j = 0; j < 64; j++) a = fmaf(hp[j], wc[j], a);
        g_feat[(s0 + s) * 4 + c] = a;
    }
}

// ---------------------------------------------------------------------------
// K3: batch mean/var -> scale/shift
// ---------------------------------------------------------------------------
__global__ void k_stats(const float* __restrict__ bn_g,
                        const float* __restrict__ bn_b) {
    __shared__ double ss[256][8];
    const int tid = threadIdx.x;
    double sum[4] = {0, 0, 0, 0}, sq[4] = {0, 0, 0, 0};
    for (int s = tid; s < BATCH; s += 256) {
        float4 f = ((const float4*)g_feat)[s];
        double v;
        v = (double)f.x; sum[0] += v; sq[0] += v * v;
        v = (double)f.y; sum[1] += v; sq[1] += v * v;
        v = (double)f.z; sum[2] += v; sq[2] += v * v;
        v = (double)f.w; sum[3] += v; sq[3] += v * v;
    }
    #pragma unroll
    for (int c = 0; c < 4; c++) { ss[tid][c] = sum[c]; ss[tid][4 + c] = sq[c]; }
    __syncthreads();
    for (int off = 128; off >= 1; off >>= 1) {
        if (tid < off) {
            #pragma unroll
            for (int k = 0; k < 8; k++) ss[tid][k] += ss[tid + off][k];
        }
        __syncthreads();
    }
    if (tid < 4) {
        double m = ss[0][tid] / (double)BATCH;
        double var = ss[0][4 + tid] / (double)BATCH - m * m;
        float scale = (float)((double)bn_g[tid] / sqrt(var + 1e-5));
        float shift = bn_b[tid] - (float)m * scale;
        g_scsh[tid] = scale;
        g_scsh[4 + tid] = shift;
    }
}

// ---------------------------------------------------------------------------
// K4: quantum state-vector sim + PauliZ measurement
// ---------------------------------------------------------------------------
template <int STR>
__device__ __forceinline__ void rot_rx(float* sr, float* si, float c, float s) {
    #pragma unroll
    for (int k = 0; k < 16; k++) {
        if (k & STR) continue;
        int k1 = k | STR;
        float ar0 = sr[k], ai0 = si[k], ar1 = sr[k1], ai1 = si[k1];
        sr[k]  = c * ar0 + s * ai1;
        si[k]  = c * ai0 - s * ar1;
        sr[k1] = s * ai0 + c * ar1;
        si[k1] = -s * ar0 + c * ai1;
    }
}

template <int STR>
__device__ __forceinline__ void rot_ry(float* sr, float* si, float c, float s) {
    #pragma unroll
    for (int k = 0; k < 16; k++) {
        if (k & STR) continue;
        int k1 = k | STR;
        float ar0 = sr[k], ai0 = si[k], ar1 = sr[k1], ai1 = si[k1];
        sr[k]  = c * ar0 - s * ar1;
        si[k]  = c * ai0 - s * ai1;
        sr[k1] = s * ar0 + c * ar1;
        si[k1] = s * ai0 + c * ai1;
    }
}

template <int STR>
__device__ __forceinline__ void rot_rz(float* sr, float* si, float c, float s) {
    #pragma unroll
    for (int k = 0; k < 16; k++) {
        float ar = sr[k], ai = si[k];
        if (k & STR) { sr[k] = c * ar - s * ai; si[k] = c * ai + s * ar; }
        else         { sr[k] = c * ar + s * ai; si[k] = c * ai - s * ar; }
    }
}

__device__ __forceinline__ void cnot_c3_t0(float* sr, float* si) {
    #pragma unroll
    for (int k = 1; k < 8; k += 2) {
        int k1 = k | 8;
        float tr = sr[k], ti = si[k];
        sr[k] = sr[k1]; si[k] = si[k1];
        sr[k1] = tr;    si[k1] = ti;
    }
}

__global__ void k_quantum(const float* __restrict__ rl_params,
                          float* __restrict__ out) {
    __shared__ float gc[23], gs[23];
    const int tid = threadIdx.x;
    if (tid < 23) {
        float t = rl_params[tid] * 0.5f;
        gc[tid] = cosf(t);
        gs[tid] = sinf(t);
    }
    __syncthreads();

    const int b = blockIdx.x * blockDim.x + tid;
    if (b >= BATCH) return;

    float sr[16], si[16];
    #pragma unroll
    for (int k = 0; k < 16; k++) { sr[k] = 0.0f; si[k] = 0.0f; }
    sr[0] = 1.0f;

    float4 f4 = ((const float4*)g_feat)[b];
    {
        float f, s, c;
        f = (f4.x * g_scsh[0] + g_scsh[4]) * 0.5f; s = sinf(f); c = cosf(f);
        rot_rx<8>(sr, si, c, s);
        f = (f4.y * g_scsh[1] + g_scsh[5]) * 0.5f; s = sinf(f); c = cosf(f);
        rot_rx<4>(sr, si, c, s);
        f = (f4.z * g_scsh[2] + g_scsh[6]) * 0.5f; s = sinf(f); c = cosf(f);
        rot_rx<2>(sr, si, c, s);
        f = (f4.w * g_scsh[3] + g_scsh[7]) * 0.5f; s = sinf(f); c = cosf(f);
        rot_rx<1>(sr, si, c, s);
    }

    #pragma unroll
    for (int r = 0; r < 7; r++) {
        rot_rx<8>(sr, si, gc[3 * r],     gs[3 * r]);
        rot_ry<4>(sr, si, gc[3 * r + 1], gs[3 * r + 1]);
        rot_rz<2>(sr, si, gc[3 * r + 2], gs[3 * r + 2]);
        cnot_c3_t0(sr, si);
    }
    rot_rx<8>(sr, si, gc[21], gs[21]);
    rot_ry<4>(sr, si, gc[22], gs[22]);

    float p[16];
    #pragma unroll
    for (int k = 0; k < 16; k++) p[k] = sr[k] * sr[k] + si[k] * si[k];
    #pragma unroll
    for (int w = 0; w < 4; w++) {
        int str = 8 >> w;
        float acc = 0.0f;
        #pragma unroll
        for (int k = 0; k < 16; k++) acc += (k & str) ? -p[k] : p[k];
        out[b * 4 + w] = acc;
    }
}

// ---------------------------------------------------------------------------
// Launch (3 dummies so ncu's profiled launch, index 3, is k_conv)
// ---------------------------------------------------------------------------
extern "C" void kernel_launch(void* const* d_in, const int* in_sizes, int n_in,
                              void* d_out, int out_size) {
    const float* x       = (const float*)d_in[0];
    const float* conv1_w = (const float*)d_in[1];
    const float* conv1_b = (const float*)d_in[2];
    const float* conv2_w = (const float*)d_in[3];
    const float* conv2_b = (const float*)d_in[4];
    const float* fc1_w   = (const float*)d_in[5];
    const float* fc1_b   = (const float*)d_in[6];
    const float* fc2_w   = (const float*)d_in[7];
    const float* fc2_b   = (const float*)d_in[8];
    const float* bn_g    = (const float*)d_in[9];
    const float* bn_b    = (const float*)d_in[10];
    const float* rl      = (const float*)d_in[11];
    float* out = (float*)d_out;

    k_nop<<<1, 32>>>();
    k_nop<<<1, 32>>>();
    k_nop<<<1, 32>>>();
    k_conv<<<BATCH / 2, 224>>>(x, conv1_w, conv1_b, conv2_w, conv2_b);
    k_fc<<<BATCH / 64, 256>>>(fc1_w, fc1_b, fc2_w, fc2_b);
    k_stats<<<1, 256>>>(bn_g, bn_b);
    k_quantum<<<BATCH / 256, 256>>>(rl, out);
}

// round 15
// speedup vs baseline: 1.2775x; 1.2437x over previous
#include <cuda_runtime.h>
#include <math.h>

#define BATCH 8192

// sp layout constants (bank-conflict-free padded layout)
#define RS 20            // row stride in floats
#define PS 324           // plane (channel) stride
#define SS (8 * PS)      // sample stride: 2592 floats

// ---------------------------------------------------------------------------
// Scratch
// ---------------------------------------------------------------------------
__device__ __align__(16) float g_flat[BATCH * 784]; // conv2 output [B,784]
__device__ __align__(16) float g_feat[BATCH * 4];   // fc2 output   [B,4]
__device__ float g_scsh[8];                         // [scale, shift]

// ---------------------------------------------------------------------------
// K1: fused conv1+pool, conv2+pool. 2 samples/block, 224 threads (R7-proven,
// at the scalar-FFMA issue wall). All inner loads LDS.128; STG.128 out.
// ---------------------------------------------------------------------------
__global__ __launch_bounds__(224, 4)
void k_conv(const float* __restrict__ x,
            const float* __restrict__ w1, const float* __restrict__ b1,
            const float* __restrict__ w2, const float* __restrict__ b2) {
    __shared__ __align__(16) float sx[2][30][32];   // padded input (1920 f)
    __shared__ __align__(16) float sp[2 * SS];      // conv1 pooled out (5184 f)
    __shared__ __align__(16) float sw1p[96];        // conv1 w, [oc][12]
    __shared__ __align__(16) float sw2p[1600];      // conv2 w, [oc]*100 + [ic]*12
    __shared__ __align__(16) float sflat[2 * 784];  // output staging
    __shared__ float sb1[8], sb2[16];

    const int tid = threadIdx.x;
    const int b0 = blockIdx.x * 2;

    for (int i = tid; i < 1920; i += 224) ((float*)sx)[i] = 0.0f;
    for (int i = tid; i < 2 * SS; i += 224) sp[i] = 0.0f;
    for (int i = tid; i < 1152; i += 224) {
        int oc = i / 72, rem = i % 72, ic = rem / 9, j = rem % 9;
        sw2p[oc * 100 + ic * 12 + j] = w2[i];
    }
    if (tid < 72) sw1p[(tid / 9) * 12 + (tid % 9)] = w1[tid];
    if (tid < 8)  sb1[tid] = b1[tid];
    if (tid < 16) sb2[tid] = b2[tid];
    __syncthreads();

    for (int i = tid; i < 2 * 784; i += 224) {
        int s = i / 784, r = i % 784;
        sx[s][r / 28 + 1][r % 28 + 1] = x[(b0 + s) * 784 + r];
    }
    __syncthreads();

    // -------- conv1 (1->8) + relu + pool -> sp --------
    {
        const int oc = tid & 7;
        const int rest = tid >> 3;      // 0..27
        const int y2 = rest % 14;
        const int s = rest / 14;
        float4 wa = *(const float4*)&sw1p[oc * 12];
        float4 wb = *(const float4*)&sw1p[oc * 12 + 4];
        float4 wc = *(const float4*)&sw1p[oc * 12 + 8];
        const float w[9] = {wa.x, wa.y, wa.z, wa.w, wb.x, wb.y, wb.z, wb.w, wc.x};
        const float bias = sb1[oc];
        float* spb = &sp[s * SS + oc * PS + (y2 + 1) * RS];

        #pragma unroll
        for (int xh = 0; xh < 2; xh++) {
            const int SH = xh * 2;
            float a0[14], a1[14];
            #pragma unroll
            for (int i2 = 0; i2 < 14; i2++) { a0[i2] = bias; a1[i2] = bias; }

            #pragma unroll
            for (int r = 0; r < 4; r++) {
                float e[20];
                const float* rp = &sx[s][2 * y2 + r][xh * 12];
                #pragma unroll
                for (int q = 0; q < 5; q++) ((float4*)e)[q] = ((const float4*)rp)[q];
                if (r < 3) {
                    #pragma unroll
                    for (int xx = 0; xx < 14; xx++) {
                        float a = a0[xx];
                        a = fmaf(e[xx + SH],     w[3 * r],     a);
                        a = fmaf(e[xx + SH + 1], w[3 * r + 1], a);
                        a = fmaf(e[xx + SH + 2], w[3 * r + 2], a);
                        a0[xx] = a;
                    }
                }
                if (r >= 1) {
                    #pragma unroll
                    for (int xx = 0; xx < 14; xx++) {
                        float a = a1[xx];
                        a = fmaf(e[xx + SH],     w[3 * (r - 1)],     a);
                        a = fmaf(e[xx + SH + 1], w[3 * (r - 1) + 1], a);
                        a = fmaf(e[xx + SH + 2], w[3 * (r - 1) + 2], a);
                        a1[xx] = a;
                    }
                }
            }
            #pragma unroll
            for (int p = 0; p < 7; p++) {
                float a = fmaxf(a0[2 * p], 0.0f);
                a = fmaxf(a, fmaxf(a0[2 * p + 1], 0.0f));
                a = fmaxf(a, fmaxf(a1[2 * p], 0.0f));
                a = fmaxf(a, fmaxf(a1[2 * p + 1], 0.0f));
                spb[xh * 7 + p + 1] = a;
            }
        }
    }
    __syncthreads();

    // -------- conv2 (8->16) + relu + pool -> sflat -> g_flat --------
    {
        const int oc = tid & 15;
        const int rest = tid >> 4;     // 0..13
        const int y2 = rest % 7;
        const int s = rest / 7;
        const float bias = sb2[oc];
        float acc0[14], acc1[14];
        #pragma unroll
        for (int i2 = 0; i2 < 14; i2++) { acc0[i2] = bias; acc1[i2] = bias; }

        #pragma unroll
        for (int ic = 0; ic < 8; ic++) {
            const float* wp = &sw2p[oc * 100 + ic * 12];
            float4 wa = *(const float4*)(wp);
            float4 wb = *(const float4*)(wp + 4);
            float4 wc = *(const float4*)(wp + 8);
            const float w[9] = {wa.x, wa.y, wa.z, wa.w, wb.x, wb.y, wb.z, wb.w, wc.x};

            const float* rowp = &sp[s * SS + ic * PS + (2 * y2) * RS];
            #pragma unroll
            for (int r = 0; r < 4; r++) {
                float e[16];
                #pragma unroll
                for (int q = 0; q < 4; q++)
                    ((float4*)e)[q] = ((const float4*)(rowp + r * RS))[q];
                if (r < 3) {
                    #pragma unroll
                    for (int xx = 0; xx < 14; xx++) {
                        float a = acc0[xx];
                        a = fmaf(e[xx],     w[3 * r],     a);
                        a = fmaf(e[xx + 1], w[3 * r + 1], a);
                        a = fmaf(e[xx + 2], w[3 * r + 2], a);
                        acc0[xx] = a;
                    }
                }
                if (r >= 1) {
                    #pragma unroll
                    for (int xx = 0; xx < 14; xx++) {
                        float a = acc1[xx];
                        a = fmaf(e[xx],     w[3 * (r - 1)],     a);
                        a = fmaf(e[xx + 1], w[3 * (r - 1) + 1], a);
                        a = fmaf(e[xx + 2], w[3 * (r - 1) + 2], a);
                        acc1[xx] = a;
                    }
                }
            }
        }

        float* stg = &sflat[s * 784 + oc * 49 + y2 * 7];
        #pragma unroll
        for (int p = 0; p < 7; p++) {
            float a = fmaxf(acc0[2 * p], 0.0f);
            a = fmaxf(a, fmaxf(acc0[2 * p + 1], 0.0f));
            a = fmaxf(a, fmaxf(acc1[2 * p], 0.0f));
            a = fmaxf(a, fmaxf(acc1[2 * p + 1], 0.0f));
            stg[p] = a;
        }
    }
    __syncthreads();

    {
        float4* dst = (float4*)&g_flat[b0 * 784];
        const float4* src = (const float4*)sflat;
        for (int i = tid; i < 392; i += 224) dst[i] = src[i];
    }
}

// ---------------------------------------------------------------------------
// K2: FC1(784->64)+relu + FC2(64->4), tiled GEMM, register prefetch +
// ping-pong double buffering (ONE sync per k-tile).
// ---------------------------------------------------------------------------
#define FCS 60
#define FCBUF (2 * 64 * FCS)   // one buffer: sA[64*60] | sW[64*60]
__global__ __launch_bounds__(256)
void k_fc(const float* __restrict__ fc1_w, const float* __restrict__ fc1_b,
          const float* __restrict__ fc2_w, const float* __restrict__ fc2_b) {
    __shared__ __align__(16) float sAW[2 * FCBUF];  // ping-pong buffers
    __shared__ float sw2[256];

    const int tid = threadIdx.x;
    const int s0 = blockIdx.x * 64;
    const int jj = tid & 31;     // output pair {jj, jj+32}
    const int ss = tid >> 5;     // sample group: samples ss*8 .. ss*8+7

    sw2[tid] = fc2_w[tid];

    // per-thread staging plan: 7 float4 per tile (1792 total = 2 x 64 x 14)
    const float* src[7];
    int dst[7];
    #pragma unroll
    for (int j = 0; j < 7; j++) {
        int i = tid + 256 * j;
        if (i < 896) {
            int r = i / 14, q = i % 14;
            src[j] = &g_flat[(s0 + r) * 784 + q * 4];
            dst[j] = r * FCS + q * 4;
        } else {
            int i2 = i - 896;
            int r = i2 / 14, q = i2 % 14;
            src[j] = &fc1_w[r * 784 + q * 4];
            dst[j] = 64 * FCS + r * FCS + q * 4;
        }
    }

    float4 pf[7];
    #pragma unroll
    for (int j = 0; j < 7; j++) { pf[j] = *(const float4*)src[j]; src[j] += 56; }

    float acc[2][8];
    #pragma unroll
    for (int u = 0; u < 8; u++) { acc[0][u] = 0.0f; acc[1][u] = 0.0f; }

    int buf = 0;
    for (int t = 0; t < 14; t++) {
        float* sb = &sAW[buf * FCBUF];
        #pragma unroll
        for (int j = 0; j < 7; j++) *(float4*)&sb[dst[j]] = pf[j];
        // prefetch next tile while waiting at the barrier
        if (t < 13) {
            #pragma unroll
            for (int j = 0; j < 7; j++) { pf[j] = *(const float4*)src[j]; src[j] += 56; }
        }
        __syncthreads();
        const float* sA = sb;
        const float* sW = sb + 64 * FCS;
        #pragma unroll
        for (int k4 = 0; k4 < 14; k4++) {
            float4 w0 = *(const float4*)&sW[jj * FCS + k4 * 4];
            float4 w1 = *(const float4*)&sW[(jj + 32) * FCS + k4 * 4];
            #pragma unroll
            for (int u = 0; u < 8; u++) {
                float4 a = *(const float4*)&sA[(ss * 8 + u) * FCS + k4 * 4];
                float t0 = acc[0][u], t1 = acc[1][u];
                t0 = fmaf(a.x, w0.x, t0); t1 = fmaf(a.x, w1.x, t1);
                t0 = fmaf(a.y, w0.y, t0); t1 = fmaf(a.y, w1.y, t1);
                t0 = fmaf(a.z, w0.z, t0); t1 = fmaf(a.z, w1.z, t1);
                t0 = fmaf(a.w, w0.w, t0); t1 = fmaf(a.w, w1.w, t1);
                acc[0][u] = t0; acc[1][u] = t1;
            }
        }
        buf ^= 1;
    }

    __syncthreads();
    float* sh = sAW;   // reuse buffer 0: 64 samples x stride 65
    const float bj0 = fc1_b[jj], bj1 = fc1_b[jj + 32];
    #pragma unroll
    for (int u = 0; u < 8; u++) {
        sh[(ss * 8 + u) * 65 + jj]      = fmaxf(acc[0][u] + bj0, 0.0f);
        sh[(ss * 8 + u) * 65 + jj + 32] = fmaxf(acc[1][u] + bj1, 0.0f);
    }
    __syncthreads();

    {
        const int s = tid >> 2, c = tid & 3;
        float a = fc2_b[c];
        const float* hp = &sh[s * 65];
        const float* wc = &sw2[c * 64];
        #pragma unroll
        for (int j = 0; j < 64; j++) a = fmaf(hp[j], wc[j], a);
        g_feat[(s0 + s) * 4 + c] = a;
    }
}

// ---------------------------------------------------------------------------
// K3: batch mean/var -> scale/shift
// ---------------------------------------------------------------------------
__global__ void k_stats(const float* __restrict__ bn_g,
                        const float* __restrict__ bn_b) {
    __shared__ double ss[256][8];
    const int tid = threadIdx.x;
    double sum[4] = {0, 0, 0, 0}, sq[4] = {0, 0, 0, 0};
    for (int s = tid; s < BATCH; s += 256) {
        float4 f = ((const float4*)g_feat)[s];
        double v;
        v = (double)f.x; sum[0] += v; sq[0] += v * v;
        v = (double)f.y; sum[1] += v; sq[1] += v * v;
        v = (double)f.z; sum[2] += v; sq[2] += v * v;
        v = (double)f.w; sum[3] += v; sq[3] += v * v;
    }
    #pragma unroll
    for (int c = 0; c < 4; c++) { ss[tid][c] = sum[c]; ss[tid][4 + c] = sq[c]; }
    __syncthreads();
    for (int off = 128; off >= 1; off >>= 1) {
        if (tid < off) {
            #pragma unroll
            for (int k = 0; k < 8; k++) ss[tid][k] += ss[tid + off][k];
        }
        __syncthreads();
    }
    if (tid < 4) {
        double m = ss[0][tid] / (double)BATCH;
        double var = ss[0][4 + tid] / (double)BATCH - m * m;
        float scale = (float)((double)bn_g[tid] / sqrt(var + 1e-5));
        float shift = bn_b[tid] - (float)m * scale;
        g_scsh[tid] = scale;
        g_scsh[4 + tid] = shift;
    }
}

// ---------------------------------------------------------------------------
// K4: quantum state-vector sim + PauliZ measurement
// ---------------------------------------------------------------------------
template <int STR>
__device__ __forceinline__ void rot_rx(float* sr, float* si, float c, float s) {
    #pragma unroll
    for (int k = 0; k < 16; k++) {
        if (k & STR) continue;
        int k1 = k | STR;
        float ar0 = sr[k], ai0 = si[k], ar1 = sr[k1], ai1 = si[k1];
        sr[k]  = c * ar0 + s * ai1;
        si[k]  = c * ai0 - s * ar1;
        sr[k1] = s * ai0 + c * ar1;
        si[k1] = -s * ar0 + c * ai1;
    }
}

template <int STR>
__device__ __forceinline__ void rot_ry(float* sr, float* si, float c, float s) {
    #pragma unroll
    for (int k = 0; k < 16; k++) {
        if (k & STR) continue;
        int k1 = k | STR;
        float ar0 = sr[k], ai0 = si[k], ar1 = sr[k1], ai1 = si[k1];
        sr[k]  = c * ar0 - s * ar1;
        si[k]  = c * ai0 - s * ai1;
        sr[k1] = s * ar0 + c * ar1;
        si[k1] = s * ai0 + c * ai1;
    }
}

template <int STR>
__device__ __forceinline__ void rot_rz(float* sr, float* si, float c, float s) {
    #pragma unroll
    for (int k = 0; k < 16; k++) {
        float ar = sr[k], ai = si[k];
        if (k & STR) { sr[k] = c * ar - s * ai; si[k] = c * ai + s * ar; }
        else         { sr[k] = c * ar + s * ai; si[k] = c * ai - s * ar; }
    }
}

__device__ __forceinline__ void cnot_c3_t0(float* sr, float* si) {
    #pragma unroll
    for (int k = 1; k < 8; k += 2) {
        int k1 = k | 8;
        float tr = sr[k], ti = si[k];
        sr[k] = sr[k1]; si[k] = si[k1];
        sr[k1] = tr;    si[k1] = ti;
    }
}

__global__ void k_quantum(const float* __restrict__ rl_params,
                          float* __restrict__ out) {
    __shared__ float gc[23], gs[23];
    const int tid = threadIdx.x;
    if (tid < 23) {
        float t = rl_params[tid] * 0.5f;
        gc[tid] = cosf(t);
        gs[tid] = sinf(t);
    }
    __syncthreads();

    const int b = blockIdx.x * blockDim.x + tid;
    if (b >= BATCH) return;

    float sr[16], si[16];
    #pragma unroll
    for (int k = 0; k < 16; k++) { sr[k] = 0.0f; si[k] = 0.0f; }
    sr[0] = 1.0f;

    float4 f4 = ((const float4*)g_feat)[b];
    {
        float f, s, c;
        f = (f4.x * g_scsh[0] + g_scsh[4]) * 0.5f; s = sinf(f); c = cosf(f);
        rot_rx<8>(sr, si, c, s);
        f = (f4.y * g_scsh[1] + g_scsh[5]) * 0.5f; s = sinf(f); c = cosf(f);
        rot_rx<4>(sr, si, c, s);
        f = (f4.z * g_scsh[2] + g_scsh[6]) * 0.5f; s = sinf(f); c = cosf(f);
        rot_rx<2>(sr, si, c, s);
        f = (f4.w * g_scsh[3] + g_scsh[7]) * 0.5f; s = sinf(f); c = cosf(f);
        rot_rx<1>(sr, si, c, s);
    }

    #pragma unroll
    for (int r = 0; r < 7; r++) {
        rot_rx<8>(sr, si, gc[3 * r],     gs[3 * r]);
        rot_ry<4>(sr, si, gc[3 * r + 1], gs[3 * r + 1]);
        rot_rz<2>(sr, si, gc[3 * r + 2], gs[3 * r + 2]);
        cnot_c3_t0(sr, si);
    }
    rot_rx<8>(sr, si, gc[21], gs[21]);
    rot_ry<4>(sr, si, gc[22], gs[22]);

    float p[16];
    #pragma unroll
    for (int k = 0; k < 16; k++) p[k] = sr[k] * sr[k] + si[k] * si[k];
    #pragma unroll
    for (int w = 0; w < 4; w++) {
        int str = 8 >> w;
        float acc = 0.0f;
        #pragma unroll
        for (int k = 0; k < 16; k++) acc += (k & str) ? -p[k] : p[k];
        out[b * 4 + w] = acc;
    }
}

// ---------------------------------------------------------------------------
// Launch
// ---------------------------------------------------------------------------
extern "C" void kernel_launch(void* const* d_in, const int* in_sizes, int n_in,
                              void* d_out, int out_size) {
    const float* x       = (const float*)d_in[0];
    const float* conv1_w = (const float*)d_in[1];
    const float* conv1_b = (const float*)d_in[2];
    const float* conv2_w = (const float*)d_in[3];
    const float* conv2_b = (const float*)d_in[4];
    const float* fc1_w   = (const float*)d_in[5];
    const float* fc1_b   = (const float*)d_in[6];
    const float* fc2_w   = (const float*)d_in[7];
    const float* fc2_b   = (const float*)d_in[8];
    const float* bn_g    = (const float*)d_in[9];
    const float* bn_b    = (const float*)d_in[10];
    const float* rl      = (const float*)d_in[11];
    float* out = (float*)d_out;

    k_conv<<<BATCH / 2, 224>>>(x, conv1_w, conv1_b, conv2_w, conv2_b);
    k_fc<<<BATCH / 64, 256>>>(fc1_w, fc1_b, fc2_w, fc2_b);
    k_stats<<<1, 256>>>(bn_g, bn_b);
    k_quantum<<<BATCH / 256, 256>>>(rl, out);
}

// round 16
// speedup vs baseline: 1.5316x; 1.1989x over previous
#include <cuda_runtime.h>
#include <math.h>

#define BATCH 8192

// sp layout constants (bank-conflict-free padded layout)
#define RS 20            // row stride in floats
#define PS 324           // plane (channel) stride
#define SS (8 * PS)      // sample stride: 2592 floats

// ---------------------------------------------------------------------------
// Scratch
// ---------------------------------------------------------------------------
__device__ __align__(16) float g_flat[BATCH * 784]; // conv2 output [B,784]
__device__ __align__(16) float g_feat[BATCH * 4];   // fc2 output   [B,4]
__device__ double g_part[128][8];                   // per-fc-block BN partials

// ---------------------------------------------------------------------------
// K1: fused conv1+pool, conv2+pool. 2 samples/block, 224 threads (R7-proven,
// at the scalar-FFMA issue wall). All inner loads LDS.128; STG.128 out.
// ---------------------------------------------------------------------------
__global__ __launch_bounds__(224, 4)
void k_conv(const float* __restrict__ x,
            const float* __restrict__ w1, const float* __restrict__ b1,
            const float* __restrict__ w2, const float* __restrict__ b2) {
    __shared__ __align__(16) float sx[2][30][32];   // padded input (1920 f)
    __shared__ __align__(16) float sp[2 * SS];      // conv1 pooled out (5184 f)
    __shared__ __align__(16) float sw1p[96];        // conv1 w, [oc][12]
    __shared__ __align__(16) float sw2p[1600];      // conv2 w, [oc]*100 + [ic]*12
    __shared__ __align__(16) float sflat[2 * 784];  // output staging
    __shared__ float sb1[8], sb2[16];

    const int tid = threadIdx.x;
    const int b0 = blockIdx.x * 2;

    for (int i = tid; i < 1920; i += 224) ((float*)sx)[i] = 0.0f;
    for (int i = tid; i < 2 * SS; i += 224) sp[i] = 0.0f;
    for (int i = tid; i < 1152; i += 224) {
        int oc = i / 72, rem = i % 72, ic = rem / 9, j = rem % 9;
        sw2p[oc * 100 + ic * 12 + j] = w2[i];
    }
    if (tid < 72) sw1p[(tid / 9) * 12 + (tid % 9)] = w1[tid];
    if (tid < 8)  sb1[tid] = b1[tid];
    if (tid < 16) sb2[tid] = b2[tid];
    __syncthreads();

    for (int i = tid; i < 2 * 784; i += 224) {
        int s = i / 784, r = i % 784;
        sx[s][r / 28 + 1][r % 28 + 1] = x[(b0 + s) * 784 + r];
    }
    __syncthreads();

    // -------- conv1 (1->8) + relu + pool -> sp --------
    {
        const int oc = tid & 7;
        const int rest = tid >> 3;      // 0..27
        const int y2 = rest % 14;
        const int s = rest / 14;
        float4 wa = *(const float4*)&sw1p[oc * 12];
        float4 wb = *(const float4*)&sw1p[oc * 12 + 4];
        float4 wc = *(const float4*)&sw1p[oc * 12 + 8];
        const float w[9] = {wa.x, wa.y, wa.z, wa.w, wb.x, wb.y, wb.z, wb.w, wc.x};
        const float bias = sb1[oc];
        float* spb = &sp[s * SS + oc * PS + (y2 + 1) * RS];

        #pragma unroll
        for (int xh = 0; xh < 2; xh++) {
            const int SH = xh * 2;
            float a0[14], a1[14];
            #pragma unroll
            for (int i2 = 0; i2 < 14; i2++) { a0[i2] = bias; a1[i2] = bias; }

            #pragma unroll
            for (int r = 0; r < 4; r++) {
                float e[20];
                const float* rp = &sx[s][2 * y2 + r][xh * 12];
                #pragma unroll
                for (int q = 0; q < 5; q++) ((float4*)e)[q] = ((const float4*)rp)[q];
                if (r < 3) {
                    #pragma unroll
                    for (int xx = 0; xx < 14; xx++) {
                        float a = a0[xx];
                        a = fmaf(e[xx + SH],     w[3 * r],     a);
                        a = fmaf(e[xx + SH + 1], w[3 * r + 1], a);
                        a = fmaf(e[xx + SH + 2], w[3 * r + 2], a);
                        a0[xx] = a;
                    }
                }
                if (r >= 1) {
                    #pragma unroll
                    for (int xx = 0; xx < 14; xx++) {
                        float a = a1[xx];
                        a = fmaf(e[xx + SH],     w[3 * (r - 1)],     a);
                        a = fmaf(e[xx + SH + 1], w[3 * (r - 1) + 1], a);
                        a = fmaf(e[xx + SH + 2], w[3 * (r - 1) + 2], a);
                        a1[xx] = a;
                    }
                }
            }
            #pragma unroll
            for (int p = 0; p < 7; p++) {
                float a = fmaxf(a0[2 * p], 0.0f);
                a = fmaxf(a, fmaxf(a0[2 * p + 1], 0.0f));
                a = fmaxf(a, fmaxf(a1[2 * p], 0.0f));
                a = fmaxf(a, fmaxf(a1[2 * p + 1], 0.0f));
                spb[xh * 7 + p + 1] = a;
            }
        }
    }
    __syncthreads();

    // -------- conv2 (8->16) + relu + pool -> sflat -> g_flat --------
    {
        const int oc = tid & 15;
        const int rest = tid >> 4;     // 0..13
        const int y2 = rest % 7;
        const int s = rest / 7;
        const float bias = sb2[oc];
        float acc0[14], acc1[14];
        #pragma unroll
        for (int i2 = 0; i2 < 14; i2++) { acc0[i2] = bias; acc1[i2] = bias; }

        #pragma unroll
        for (int ic = 0; ic < 8; ic++) {
            const float* wp = &sw2p[oc * 100 + ic * 12];
            float4 wa = *(const float4*)(wp);
            float4 wb = *(const float4*)(wp + 4);
            float4 wc = *(const float4*)(wp + 8);
            const float w[9] = {wa.x, wa.y, wa.z, wa.w, wb.x, wb.y, wb.z, wb.w, wc.x};

            const float* rowp = &sp[s * SS + ic * PS + (2 * y2) * RS];
            #pragma unroll
            for (int r = 0; r < 4; r++) {
                float e[16];
                #pragma unroll
                for (int q = 0; q < 4; q++)
                    ((float4*)e)[q] = ((const float4*)(rowp + r * RS))[q];
                if (r < 3) {
                    #pragma unroll
                    for (int xx = 0; xx < 14; xx++) {
                        float a = acc0[xx];
                        a = fmaf(e[xx],     w[3 * r],     a);
                        a = fmaf(e[xx + 1], w[3 * r + 1], a);
                        a = fmaf(e[xx + 2], w[3 * r + 2], a);
                        acc0[xx] = a;
                    }
                }
                if (r >= 1) {
                    #pragma unroll
                    for (int xx = 0; xx < 14; xx++) {
                        float a = acc1[xx];
                        a = fmaf(e[xx],     w[3 * (r - 1)],     a);
                        a = fmaf(e[xx + 1], w[3 * (r - 1) + 1], a);
                        a = fmaf(e[xx + 2], w[3 * (r - 1) + 2], a);
                        acc1[xx] = a;
                    }
                }
            }
        }

        float* stg = &sflat[s * 784 + oc * 49 + y2 * 7];
        #pragma unroll
        for (int p = 0; p < 7; p++) {
            float a = fmaxf(acc0[2 * p], 0.0f);
            a = fmaxf(a, fmaxf(acc0[2 * p + 1], 0.0f));
            a = fmaxf(a, fmaxf(acc1[2 * p], 0.0f));
            a = fmaxf(a, fmaxf(acc1[2 * p + 1], 0.0f));
            stg[p] = a;
        }
    }
    __syncthreads();

    {
        float4* dst = (float4*)&g_flat[b0 * 784];
        const float4* src = (const float4*)sflat;
        for (int i = tid; i < 392; i += 224) dst[i] = src[i];
    }
}

// ---------------------------------------------------------------------------
// K2: FC1(784->64)+relu + FC2(64->4), tiled GEMM, register prefetch +
// ping-pong double buffering (ONE sync per k-tile) + fused BN partial sums.
// ---------------------------------------------------------------------------
#define FCS 60
#define FCBUF (2 * 64 * FCS)   // one buffer: sA[64*60] | sW[64*60]
__global__ __launch_bounds__(256)
void k_fc(const float* __restrict__ fc1_w, const float* __restrict__ fc1_b,
          const float* __restrict__ fc2_w, const float* __restrict__ fc2_b) {
    __shared__ __align__(16) float sAW[2 * FCBUF];  // ping-pong buffers
    __shared__ float sw2[256];
    __shared__ double sred[256], sred2[256];

    const int tid = threadIdx.x;
    const int s0 = blockIdx.x * 64;
    const int jj = tid & 31;     // output pair {jj, jj+32}
    const int ss = tid >> 5;     // sample group: samples ss*8 .. ss*8+7

    sw2[tid] = fc2_w[tid];

    // per-thread staging plan: 7 float4 per tile (1792 total = 2 x 64 x 14)
    const float* src[7];
    int dst[7];
    #pragma unroll
    for (int j = 0; j < 7; j++) {
        int i = tid + 256 * j;
        if (i < 896) {
            int r = i / 14, q = i % 14;
            src[j] = &g_flat[(s0 + r) * 784 + q * 4];
            dst[j] = r * FCS + q * 4;
        } else {
            int i2 = i - 896;
            int r = i2 / 14, q = i2 % 14;
            src[j] = &fc1_w[r * 784 + q * 4];
            dst[j] = 64 * FCS + r * FCS + q * 4;
        }
    }

    float4 pf[7];
    #pragma unroll
    for (int j = 0; j < 7; j++) { pf[j] = *(const float4*)src[j]; src[j] += 56; }

    float acc[2][8];
    #pragma unroll
    for (int u = 0; u < 8; u++) { acc[0][u] = 0.0f; acc[1][u] = 0.0f; }

    int buf = 0;
    for (int t = 0; t < 14; t++) {
        float* sb = &sAW[buf * FCBUF];
        #pragma unroll
        for (int j = 0; j < 7; j++) *(float4*)&sb[dst[j]] = pf[j];
        if (t < 13) {
            #pragma unroll
            for (int j = 0; j < 7; j++) { pf[j] = *(const float4*)src[j]; src[j] += 56; }
        }
        __syncthreads();
        const float* sA = sb;
        const float* sW = sb + 64 * FCS;
        #pragma unroll
        for (int k4 = 0; k4 < 14; k4++) {
            float4 w0 = *(const float4*)&sW[jj * FCS + k4 * 4];
            float4 w1 = *(const float4*)&sW[(jj + 32) * FCS + k4 * 4];
            #pragma unroll
            for (int u = 0; u < 8; u++) {
                float4 a = *(const float4*)&sA[(ss * 8 + u) * FCS + k4 * 4];
                float t0 = acc[0][u], t1 = acc[1][u];
                t0 = fmaf(a.x, w0.x, t0); t1 = fmaf(a.x, w1.x, t1);
                t0 = fmaf(a.y, w0.y, t0); t1 = fmaf(a.y, w1.y, t1);
                t0 = fmaf(a.z, w0.z, t0); t1 = fmaf(a.z, w1.z, t1);
                t0 = fmaf(a.w, w0.w, t0); t1 = fmaf(a.w, w1.w, t1);
                acc[0][u] = t0; acc[1][u] = t1;
            }
        }
        buf ^= 1;
    }

    __syncthreads();
    float* sh = sAW;   // reuse buffer 0: 64 samples x stride 65
    const float bj0 = fc1_b[jj], bj1 = fc1_b[jj + 32];
    #pragma unroll
    for (int u = 0; u < 8; u++) {
        sh[(ss * 8 + u) * 65 + jj]      = fmaxf(acc[0][u] + bj0, 0.0f);
        sh[(ss * 8 + u) * 65 + jj + 32] = fmaxf(acc[1][u] + bj1, 0.0f);
    }
    __syncthreads();

    // FC2 + per-block BN partial sums (deterministic tree)
    {
        const int s = tid >> 2, c = tid & 3;
        float a = fc2_b[c];
        const float* hp = &sh[s * 65];
        const float* wc = &sw2[c * 64];
        #pragma unroll
        for (int j = 0; j < 64; j++) a = fmaf(hp[j], wc[j], a);
        g_feat[(s0 + s) * 4 + c] = a;
        double v = (double)a;
        sred[tid] = v;
        sred2[tid] = v * v;
    }
    __syncthreads();
    #pragma unroll
    for (int off = 128; off >= 4; off >>= 1) {
        if (tid < off) {
            sred[tid] += sred[tid + off];
            sred2[tid] += sred2[tid + off];
        }
        __syncthreads();
    }
    if (tid < 4) {
        g_part[blockIdx.x][tid] = sred[tid];
        g_part[blockIdx.x][4 + tid] = sred2[tid];
    }
}

// ---------------------------------------------------------------------------
// K3: quantum state-vector sim + PauliZ measurement, with fused BN-stat
// finalization (deterministic warp-per-channel reduction of g_part).
// ---------------------------------------------------------------------------
template <int STR>
__device__ __forceinline__ void rot_rx(float* sr, float* si, float c, float s) {
    #pragma unroll
    for (int k = 0; k < 16; k++) {
        if (k & STR) continue;
        int k1 = k | STR;
        float ar0 = sr[k], ai0 = si[k], ar1 = sr[k1], ai1 = si[k1];
        sr[k]  = c * ar0 + s * ai1;
        si[k]  = c * ai0 - s * ar1;
        sr[k1] = s * ai0 + c * ar1;
        si[k1] = -s * ar0 + c * ai1;
    }
}

template <int STR>
__device__ __forceinline__ void rot_ry(float* sr, float* si, float c, float s) {
    #pragma unroll
    for (int k = 0; k < 16; k++) {
        if (k & STR) continue;
        int k1 = k | STR;
        float ar0 = sr[k], ai0 = si[k], ar1 = sr[k1], ai1 = si[k1];
        sr[k]  = c * ar0 - s * ar1;
        si[k]  = c * ai0 - s * ai1;
        sr[k1] = s * ar0 + c * ar1;
        si[k1] = s * ai0 + c * ai1;
    }
}

template <int STR>
__device__ __forceinline__ void rot_rz(float* sr, float* si, float c, float s) {
    #pragma unroll
    for (int k = 0; k < 16; k++) {
        float ar = sr[k], ai = si[k];
        if (k & STR) { sr[k] = c * ar - s * ai; si[k] = c * ai + s * ar; }
        else         { sr[k] = c * ar + s * ai; si[k] = c * ai - s * ar; }
    }
}

__device__ __forceinline__ void cnot_c3_t0(float* sr, float* si) {
    #pragma unroll
    for (int k = 1; k < 8; k += 2) {
        int k1 = k | 8;
        float tr = sr[k], ti = si[k];
        sr[k] = sr[k1]; si[k] = si[k1];
        sr[k1] = tr;    si[k1] = ti;
    }
}

__global__ void k_quantum(const float* __restrict__ rl_params,
                          const float* __restrict__ bn_g,
                          const float* __restrict__ bn_b,
                          float* __restrict__ out) {
    __shared__ float gc[23], gs[23];
    __shared__ float gsc[8];
    __shared__ double spart[8];
    const int tid = threadIdx.x;
    if (tid < 23) {
        float t = rl_params[tid] * 0.5f;
        gc[tid] = cosf(t);
        gs[tid] = sinf(t);
    }

    // finalize BN stats: warp w reduces channel-accumulator w over 128 blocks
    {
        const int w = tid >> 5, lane = tid & 31;
        double acc = 0.0;
        #pragma unroll
        for (int j = 0; j < 4; j++) acc += g_part[lane + 32 * j][w];
        #pragma unroll
        for (int off = 16; off > 0; off >>= 1)
            acc += __shfl_down_sync(0xffffffff, acc, off);
        if (lane == 0) spart[w] = acc;
    }
    __syncthreads();
    if (tid < 4) {
        double m = spart[tid] / (double)BATCH;
        double var = spart[4 + tid] / (double)BATCH - m * m;
        float scale = (float)((double)bn_g[tid] / sqrt(var + 1e-5));
        gsc[tid] = scale;
        gsc[4 + tid] = bn_b[tid] - (float)m * scale;
    }
    __syncthreads();

    const int b = blockIdx.x * blockDim.x + tid;
    if (b >= BATCH) return;

    float sr[16], si[16];
    #pragma unroll
    for (int k = 0; k < 16; k++) { sr[k] = 0.0f; si[k] = 0.0f; }
    sr[0] = 1.0f;

    float4 f4 = ((const float4*)g_feat)[b];
    {
        float f, s, c;
        f = (f4.x * gsc[0] + gsc[4]) * 0.5f; s = sinf(f); c = cosf(f);
        rot_rx<8>(sr, si, c, s);
        f = (f4.y * gsc[1] + gsc[5]) * 0.5f; s = sinf(f); c = cosf(f);
        rot_rx<4>(sr, si, c, s);
        f = (f4.z * gsc[2] + gsc[6]) * 0.5f; s = sinf(f); c = cosf(f);
        rot_rx<2>(sr, si, c, s);
        f = (f4.w * gsc[3] + gsc[7]) * 0.5f; s = sinf(f); c = cosf(f);
        rot_rx<1>(sr, si, c, s);
    }

    #pragma unroll
    for (int r = 0; r < 7; r++) {
        rot_rx<8>(sr, si, gc[3 * r],     gs[3 * r]);
        rot_ry<4>(sr, si, gc[3 * r + 1], gs[3 * r + 1]);
        rot_rz<2>(sr, si, gc[3 * r + 2], gs[3 * r + 2]);
        cnot_c3_t0(sr, si);
    }
    rot_rx<8>(sr, si, gc[21], gs[21]);
    rot_ry<4>(sr, si, gc[22], gs[22]);

    float p[16];
    #pragma unroll
    for (int k = 0; k < 16; k++) p[k] = sr[k] * sr[k] + si[k] * si[k];
    #pragma unroll
    for (int w = 0; w < 4; w++) {
        int str = 8 >> w;
        float acc = 0.0f;
        #pragma unroll
        for (int k = 0; k < 16; k++) acc += (k & str) ? -p[k] : p[k];
        out[b * 4 + w] = acc;
    }
}

// ---------------------------------------------------------------------------
// Launch (3 kernels; stats fused away)
// ---------------------------------------------------------------------------
extern "C" void kernel_launch(void* const* d_in, const int* in_sizes, int n_in,
                              void* d_out, int out_size) {
    const float* x       = (const float*)d_in[0];
    const float* conv1_w = (const float*)d_in[1];
    const float* conv1_b = (const float*)d_in[2];
    const float* conv2_w = (const float*)d_in[3];
    const float* conv2_b = (const float*)d_in[4];
    const float* fc1_w   = (const float*)d_in[5];
    const float* fc1_b   = (const float*)d_in[6];
    const float* fc2_w   = (const float*)d_in[7];
    const float* fc2_b   = (const float*)d_in[8];
    const float* bn_g    = (const float*)d_in[9];
    const float* bn_b    = (const float*)d_in[10];
    const float* rl      = (const float*)d_in[11];
    float* out = (float*)d_out;

    k_conv<<<BATCH / 2, 224>>>(x, conv1_w, conv1_b, conv2_w, conv2_b);
    k_fc<<<BATCH / 64, 256>>>(fc1_w, fc1_b, fc2_w, fc2_b);
    k_quantum<<<BATCH / 256, 256>>>(rl, bn_g, bn_b, out);
}